// round 1
// baseline (speedup 1.0000x reference)
#include <cuda_runtime.h>

#define Bb   512
#define NN   24
#define TT   25

// ---------------- scratch (device globals: no allocation allowed) ----------------
__device__ float g_xi[Bb*NN*72];
__device__ float g_h1[Bb*NN*128];
__device__ float g_c1[Bb*NN*128];
__device__ float g_h2[Bb*NN*128];
__device__ float g_c2[Bb*NN*128];
__device__ float g_yi[Bb*NN*128];
__device__ float g_gates[Bb*NN*512];
__device__ float g_fcpre[Bb*NN*256];
__device__ float g_locstart[Bb*NN*4];

// ---------------- accurate-enough activations (overflow-safe) ----------------
__device__ __forceinline__ float sigf(float x){ return 1.0f/(1.0f+__expf(-x)); }
__device__ __forceinline__ float tanhacc(float x){
    float ax = fabsf(x);
    float e  = __expf(-2.0f*ax);         // in (0,1], no overflow
    float t  = (1.0f - e)/(1.0f + e);
    return copysignf(t, x);
}

// ---------------------------------------------------------------------------
// Per-node GEMM:  out[b,n,o_off+o] = bias[n,o] + sum_k A1[b,n,k]*W1[n,k,o]
//                                   (+ sum_k A2[b,n,k]*W2[n,k,o]  if K2>0)
// A layout: A[(b*NN+n)*K + k]   W layout: W[(n*K+k)*O + o]   bias: [n*O+o]
// grid = (NN, O/64, Bb/64), 256 threads, 64x64 tile, 4x4 per thread, KC=8
// ---------------------------------------------------------------------------
__global__ void __launch_bounds__(256) gemm_nodes(
    const float* __restrict__ A1, int K1,
    const float* __restrict__ A2, int K2,
    const float* __restrict__ W1,
    const float* __restrict__ W2,
    const float* __restrict__ bias,
    int O, int OS, int o_off,
    float* __restrict__ out)
{
    __shared__ float As[8][68];     // k-major, padded (+4) for conflict-free transpose
    __shared__ float Ws[8][64];

    const int n  = blockIdx.x;
    const int o0 = blockIdx.y << 6;
    const int b0 = blockIdx.z << 6;
    const int t  = threadIdx.x;
    const int to = t & 15,  tb  = t >> 4;
    const int lb = t >> 3,  lk  = t & 7;
    const int lo = t & 63,  lwk = t >> 6;

    float bv[4];
    #pragma unroll
    for (int j=0;j<4;j++) bv[j] = bias[n*O + o0 + to*4 + j];

    float acc[4][4];
    #pragma unroll
    for (int i=0;i<4;i++)
        #pragma unroll
        for (int j=0;j<4;j++) acc[i][j] = 0.f;

    const float* Ap = A1; const float* Wp = W1; int K = K1;
    for (int ph=0; ph<2; ph++){
        if (ph==1){ if (K2<=0) break; Ap=A2; Wp=W2; K=K2; }
        for (int k0=0; k0<K; k0+=8){
            __syncthreads();
            As[lk][lb]      = Ap[((b0+lb)*NN + n)*K + k0 + lk];
            As[lk][lb+32]   = Ap[((b0+lb+32)*NN + n)*K + k0 + lk];
            Ws[lwk][lo]     = Wp[(n*K + k0 + lwk)*O + o0 + lo];
            Ws[lwk+4][lo]   = Wp[(n*K + k0 + lwk + 4)*O + o0 + lo];
            __syncthreads();
            #pragma unroll
            for (int kk=0;kk<8;kk++){
                float4 a4 = *(const float4*)&As[kk][tb*4];
                float4 w4 = *(const float4*)&Ws[kk][to*4];
                float av[4] = {a4.x,a4.y,a4.z,a4.w};
                float wv[4] = {w4.x,w4.y,w4.z,w4.w};
                #pragma unroll
                for (int i=0;i<4;i++)
                    #pragma unroll
                    for (int j=0;j<4;j++)
                        acc[i][j] = fmaf(av[i], wv[j], acc[i][j]);
            }
        }
    }
    #pragma unroll
    for (int i=0;i<4;i++){
        float4 v = make_float4(acc[i][0]+bv[0], acc[i][1]+bv[1],
                               acc[i][2]+bv[2], acc[i][3]+bv[3]);
        *(float4*)&out[((long)(b0+tb*4+i)*NN + n)*OS + o_off + o0 + to*4] = v;
    }
}

// ---------------------------------------------------------------------------
// G-mix + LSTM cell:  gates[b,m,:] = sum_n G[m,n]*gates_pre[b,n,:]
// then c' = sig(f)*c + sig(i)*tanh(g);  h' = sig(o)*tanh(c')
// block per batch b, 256 threads, gates staged in dyn smem, 3-m register tile
// ---------------------------------------------------------------------------
__global__ void __launch_bounds__(256) lstm_mix(
    const float* __restrict__ gates, const float* __restrict__ G,
    const float* __restrict__ c_in,
    float* __restrict__ h_out, float* __restrict__ c_out,
    float* __restrict__ yi_out)
{
    extern __shared__ float smem[];
    float* sGt = smem;              // NN*512
    float* sGm = smem + NN*512;     // NN*NN

    const int b = blockIdx.x, t = threadIdx.x;
    const float* gb = gates + (long)b*NN*512;
    for (int i=t;i<NN*512;i+=256) sGt[i]=gb[i];
    for (int i=t;i<NN*NN;i+=256)  sGm[i]=G[i];
    __syncthreads();

    const int ocg = t & 31;    // oc = ocg*4
    const int mg  = t >> 5;    // 8 groups x 3 m = 24
    const float4* s4 = (const float4*)sGt;

    float ai[3][4], af[3][4], ag[3][4], ao[3][4];
    #pragma unroll
    for (int mm=0;mm<3;mm++)
        #pragma unroll
        for (int j=0;j<4;j++){ ai[mm][j]=0.f; af[mm][j]=0.f; ag[mm][j]=0.f; ao[mm][j]=0.f; }

    #pragma unroll 4
    for (int n=0;n<NN;n++){
        float4 vi = s4[n*128       + ocg];
        float4 vf = s4[n*128 + 32  + ocg];
        float4 vg = s4[n*128 + 64  + ocg];
        float4 vo = s4[n*128 + 96  + ocg];
        #pragma unroll
        for (int mm=0;mm<3;mm++){
            float g = sGm[(mg*3+mm)*NN + n];
            ai[mm][0]=fmaf(g,vi.x,ai[mm][0]); ai[mm][1]=fmaf(g,vi.y,ai[mm][1]);
            ai[mm][2]=fmaf(g,vi.z,ai[mm][2]); ai[mm][3]=fmaf(g,vi.w,ai[mm][3]);
            af[mm][0]=fmaf(g,vf.x,af[mm][0]); af[mm][1]=fmaf(g,vf.y,af[mm][1]);
            af[mm][2]=fmaf(g,vf.z,af[mm][2]); af[mm][3]=fmaf(g,vf.w,af[mm][3]);
            ag[mm][0]=fmaf(g,vg.x,ag[mm][0]); ag[mm][1]=fmaf(g,vg.y,ag[mm][1]);
            ag[mm][2]=fmaf(g,vg.z,ag[mm][2]); ag[mm][3]=fmaf(g,vg.w,ag[mm][3]);
            ao[mm][0]=fmaf(g,vo.x,ao[mm][0]); ao[mm][1]=fmaf(g,vo.y,ao[mm][1]);
            ao[mm][2]=fmaf(g,vo.z,ao[mm][2]); ao[mm][3]=fmaf(g,vo.w,ao[mm][3]);
        }
    }
    #pragma unroll
    for (int mm=0;mm<3;mm++){
        int m = mg*3+mm;
        long base = ((long)b*NN + m)*128 + ocg*4;
        float4 co = *(const float4*)&c_in[base];
        float cold[4] = {co.x,co.y,co.z,co.w};
        float cn[4], hn[4];
        #pragma unroll
        for (int j=0;j<4;j++){
            cn[j] = sigf(af[mm][j])*cold[j] + sigf(ai[mm][j])*tanhacc(ag[mm][j]);
            hn[j] = sigf(ao[mm][j])*tanhacc(cn[j]);
        }
        *(float4*)&c_out[base] = make_float4(cn[0],cn[1],cn[2],cn[3]);
        *(float4*)&h_out[base] = make_float4(hn[0],hn[1],hn[2],hn[3]);
        if (yi_out)
            *(float4*)&yi_out[base] = make_float4(tanhacc(hn[0]),tanhacc(hn[1]),
                                                  tanhacc(hn[2]),tanhacc(hn[3]));
    }
}

// ---------------------------------------------------------------------------
// Head: yi1/yi2 = tanh(Gmix(fcpre)); p = proj(loc_W / logz_W); Gmix; normalize
// quaternion; quat_mul with loc_start; write outputs; rebuild xi[64:72].
// block per batch b, 256 threads
// ---------------------------------------------------------------------------
__global__ void __launch_bounds__(256) head_kernel(
    const float* __restrict__ G,
    const float* __restrict__ locW, const float* __restrict__ locB,
    const float* __restrict__ lzW,  const float* __restrict__ lzB,
    float* __restrict__ out, int tstep)
{
    extern __shared__ float smem[];
    float* sP  = smem;                 // 6144 (fcpre[b])
    float* sY  = sP  + NN*256;         // 6144 (yi1|yi2)
    float* sG  = sY  + NN*256;         // 576
    float* sQ  = sG  + NN*NN;          // 24*8
    float* sLW = sQ  + NN*8;           // 384
    float* sLZ = sLW + 128*3;          // 512

    const int b = blockIdx.x, t = threadIdx.x;
    const float* pb = g_fcpre + (long)b*NN*256;
    for (int i=t;i<NN*256;i+=256) sP[i]=pb[i];
    for (int i=t;i<NN*NN;i+=256)  sG[i]=G[i];
    for (int i=t;i<384;i+=256)    sLW[i]=locW[i];
    for (int i=t;i<512;i+=256)    sLZ[i]=lzW[i];
    __syncthreads();

    // mix + tanh: 24m x 256oc, 6-m register tile
    {
        const int ocg = t & 63;        // oc = ocg*4 over 256
        const int mg  = t >> 6;        // 4 groups x 6 m
        const float4* p4 = (const float4*)sP;
        float acc[6][4];
        #pragma unroll
        for (int mm=0;mm<6;mm++)
            #pragma unroll
            for (int j=0;j<4;j++) acc[mm][j]=0.f;
        #pragma unroll 4
        for (int n=0;n<NN;n++){
            float4 v = p4[n*64 + ocg];
            #pragma unroll
            for (int mm=0;mm<6;mm++){
                float g = sG[(mg*6+mm)*NN + n];
                acc[mm][0]=fmaf(g,v.x,acc[mm][0]); acc[mm][1]=fmaf(g,v.y,acc[mm][1]);
                acc[mm][2]=fmaf(g,v.z,acc[mm][2]); acc[mm][3]=fmaf(g,v.w,acc[mm][3]);
            }
        }
        #pragma unroll
        for (int mm=0;mm<6;mm++){
            int m = mg*6+mm;
            float4 v = make_float4(tanhacc(acc[mm][0]),tanhacc(acc[mm][1]),
                                   tanhacc(acc[mm][2]),tanhacc(acc[mm][3]));
            *(float4*)&sY[m*256 + ocg*4] = v;
        }
    }
    __syncthreads();

    // small projections per node
    if (t < NN*7){
        int n = t/7, j = t%7;
        float a;
        if (j < 3){
            a = locB[j];
            #pragma unroll 8
            for (int f=0;f<128;f++) a = fmaf(sY[n*256+f], sLW[f*3+j], a);
        } else {
            int j2 = j-3;
            a = lzB[j2];
            #pragma unroll 8
            for (int f=0;f<128;f++) a = fmaf(sY[n*256+128+f], sLZ[f*4+j2], a);
        }
        sQ[n*8+j] = a;
    }
    __syncthreads();

    // final G-mix + quaternion + outputs
    if (t < NN){
        int m = t;
        float s[7];
        #pragma unroll
        for (int j=0;j<7;j++){
            float a = 0.f;
            #pragma unroll 4
            for (int n=0;n<NN;n++) a = fmaf(sG[m*NN+n], sQ[n*8+j], a);
            s[j]=a;
        }
        float inv = rsqrtf(1.0f + s[0]*s[0] + s[1]*s[1] + s[2]*s[2]);
        float dw=inv, dx=s[0]*inv, dy=s[1]*inv, dz=s[2]*inv;
        long bm = (long)b*NN + m;
        float qw=g_locstart[bm*4+0], qx=g_locstart[bm*4+1],
              qy=g_locstart[bm*4+2], qz=g_locstart[bm*4+3];
        float lw = qw*dw - qx*dx - qy*dy - qz*dz;
        float lx = qw*dx + qx*dw + qy*dz - qz*dy;
        float ly = qw*dy - qx*dz + qy*dw + qz*dx;
        float lz = qw*dz + qx*dy - qy*dx + qz*dw;
        g_locstart[bm*4+0]=lw; g_locstart[bm*4+1]=lx;
        g_locstart[bm*4+2]=ly; g_locstart[bm*4+3]=lz;

        long oo = (((long)b*TT + tstep)*NN + m)*4;
        out[oo+0]=lw; out[oo+1]=lx; out[oo+2]=ly; out[oo+3]=lz;
        long oz = (long)Bb*TT*NN*4 + oo;
        out[oz+0]=s[3]; out[oz+1]=s[4]; out[oz+2]=s[5]; out[oz+3]=s[6];

        float* xi = &g_xi[bm*72 + 64];
        xi[0]=lw; xi[1]=lx; xi[2]=ly; xi[3]=lz;
        xi[4]=dw; xi[5]=dx; xi[6]=dy; xi[7]=dz;
    }
}

// ---------------------------------------------------------------------------
// init: h0/c0 = G @ (enc @ ihW + ihb)  -> h1,c1,h2,c2
// ---------------------------------------------------------------------------
__global__ void __launch_bounds__(256) init_state(
    const float* __restrict__ enc, const float* __restrict__ G,
    const float* __restrict__ W1, const float* __restrict__ b1,
    const float* __restrict__ W2, const float* __restrict__ b2)
{
    extern __shared__ float smem[];
    float* sE  = smem;             // NN*256
    float* sY1 = sE  + NN*256;     // NN*128
    float* sY2 = sY1 + NN*128;     // NN*128
    float* sG  = sY2 + NN*128;     // NN*NN

    const int b = blockIdx.x, t = threadIdx.x;
    const float* eb = enc + (long)b*NN*256;
    for (int i=t;i<NN*256;i+=256) sE[i]=eb[i];
    for (int i=t;i<NN*NN;i+=256)  sG[i]=G[i];
    __syncthreads();
    for (int idx=t; idx<NN*128; idx+=256){
        int n = idx>>7, o = idx&127;
        float a1 = b1[o], a2 = b2[o];
        for (int h=0; h<256; h++){
            float e = sE[n*256+h];
            a1 = fmaf(e, W1[h*128+o], a1);
            a2 = fmaf(e, W2[h*128+o], a2);
        }
        sY1[idx]=a1; sY2[idx]=a2;
    }
    __syncthreads();
    for (int idx=t; idx<NN*128; idx+=256){
        int m = idx>>7, o = idx&127;
        float h0=0.f, c0=0.f;
        #pragma unroll 4
        for (int n=0;n<NN;n++){
            float g = sG[m*NN+n];
            h0 = fmaf(g, sY1[n*128+o], h0);
            c0 = fmaf(g, sY2[n*128+o], c0);
        }
        long off = ((long)b*NN + m)*128 + o;
        g_h1[off]=h0; g_c1[off]=c0; g_h2[off]=h0; g_c2[off]=c0;
    }
}

__global__ void init_xi(const float* __restrict__ x, const float* __restrict__ z)
{
    int i = blockIdx.x*blockDim.x + threadIdx.x;
    if (i < Bb*NN*72){
        int f = i % 72, bn = i / 72;
        g_xi[i] = (f < 64) ? z[bn*64 + f] : x[bn*8 + (f-64)];
    }
    if (i < Bb*NN*4){
        int j = i % 4, bn = i / 4;
        g_locstart[i] = x[bn*8 + j];
    }
}

// ---------------------------------------------------------------------------
extern "C" void kernel_launch(void* const* d_in, const int* in_sizes, int n_in,
                              void* d_out, int out_size)
{
    const float* x    = (const float*)d_in[0];
    const float* enc  = (const float*)d_in[1];
    const float* z    = (const float*)d_in[2];
    /* d_in[3] = y : unused by reference */
    const float* G    = (const float*)d_in[4];
    const float* Wx0  = (const float*)d_in[5];
    const float* Wh0  = (const float*)d_in[6];
    const float* b0_  = (const float*)d_in[7];
    const float* Wx1  = (const float*)d_in[8];
    const float* Wh1  = (const float*)d_in[9];
    const float* b1_  = (const float*)d_in[10];
    const float* fcW  = (const float*)d_in[11];
    const float* fcB  = (const float*)d_in[12];
    const float* fc2W = (const float*)d_in[13];
    const float* fc2B = (const float*)d_in[14];
    const float* ih1W = (const float*)d_in[15];
    const float* ih1B = (const float*)d_in[16];
    const float* ih2W = (const float*)d_in[17];
    const float* ih2B = (const float*)d_in[18];
    const float* locW = (const float*)d_in[19];
    const float* locB = (const float*)d_in[20];
    const float* lzW  = (const float*)d_in[21];
    const float* lzB  = (const float*)d_in[22];
    float* out = (float*)d_out;

    float *p_xi,*p_h1,*p_c1,*p_h2,*p_c2,*p_yi,*p_gates,*p_fcpre;
    cudaGetSymbolAddress((void**)&p_xi, g_xi);
    cudaGetSymbolAddress((void**)&p_h1, g_h1);
    cudaGetSymbolAddress((void**)&p_c1, g_c1);
    cudaGetSymbolAddress((void**)&p_h2, g_h2);
    cudaGetSymbolAddress((void**)&p_c2, g_c2);
    cudaGetSymbolAddress((void**)&p_yi, g_yi);
    cudaGetSymbolAddress((void**)&p_gates, g_gates);
    cudaGetSymbolAddress((void**)&p_fcpre, g_fcpre);

    const int smem_lstm = (NN*512 + NN*NN)*4;
    const int smem_head = (NN*256 + NN*256 + NN*NN + NN*8 + 128*3 + 128*4)*4;
    const int smem_init = (NN*256 + NN*128 + NN*128 + NN*NN)*4;
    cudaFuncSetAttribute(lstm_mix,   cudaFuncAttributeMaxDynamicSharedMemorySize, smem_lstm);
    cudaFuncSetAttribute(head_kernel,cudaFuncAttributeMaxDynamicSharedMemorySize, smem_head);
    cudaFuncSetAttribute(init_state, cudaFuncAttributeMaxDynamicSharedMemorySize, smem_init);

    init_state<<<Bb, 256, smem_init>>>(enc, G, ih1W, ih1B, ih2W, ih2B);
    init_xi<<<(Bb*NN*72 + 255)/256, 256>>>(x, z);

    dim3 gl(NN, 8, Bb/64);   // lstm gemms: O=512
    dim3 gf(NN, 2, Bb/64);   // fc gemms:  O=128

    for (int t = 0; t < TT; t++){
        gemm_nodes<<<gl, 256>>>(p_xi, 72,  p_h1, 128, Wx0, Wh0, b0_, 512, 512, 0,   p_gates);
        lstm_mix  <<<Bb, 256, smem_lstm>>>(p_gates, G, p_c1, p_h1, p_c1, nullptr);
        gemm_nodes<<<gl, 256>>>(p_h1, 128, p_h2, 128, Wx1, Wh1, b1_, 512, 512, 0,   p_gates);
        lstm_mix  <<<Bb, 256, smem_lstm>>>(p_gates, G, p_c2, p_h2, p_c2, p_yi);
        gemm_nodes<<<gf, 256>>>(p_yi, 128, nullptr, 0, fcW,  nullptr, fcB,  128, 256, 0,   p_fcpre);
        gemm_nodes<<<gf, 256>>>(p_yi, 128, nullptr, 0, fc2W, nullptr, fc2B, 128, 256, 128, p_fcpre);
        head_kernel<<<Bb, 256, smem_head>>>(G, locW, locB, lzW, lzB, out, t);
    }
}

// round 2
// speedup vs baseline: 1.1661x; 1.1661x over previous
#include <cuda_runtime.h>
#include <cstdint>

#define Bb   512
#define NN   24
#define TT   25

// ---------------- scratch (device globals) ----------------
// node-major activations: X[(n*Bb + b)*F + f]
__device__ float g_xi[NN*Bb*72];
__device__ float g_h1[NN*Bb*128];
__device__ float g_c1[NN*Bb*128];
__device__ float g_h2[NN*Bb*128];
__device__ float g_c2[NN*Bb*128];
__device__ float g_yi[NN*Bb*128];
__device__ float g_gates[NN*Bb*512];
__device__ float g_fcpre[NN*Bb*256];
__device__ float g_locstart[Bb*NN*4];     // b-major (head convenience)

// ---------------- activations ----------------
__device__ __forceinline__ float sigf(float x){ return 1.0f/(1.0f+__expf(-x)); }
__device__ __forceinline__ float tanhacc(float x){
    float ax = fabsf(x);
    float e  = __expf(-2.0f*ax);
    float t  = (1.0f - e)/(1.0f + e);
    return copysignf(t, x);
}

// ---------------- tf32 helpers ----------------
__device__ __forceinline__ uint32_t f2tf32(float x){
    uint32_t r; asm("cvt.rna.tf32.f32 %0, %1;" : "=r"(r) : "f"(x)); return r;
}
__device__ __forceinline__ void mma8(float* c, const uint32_t* a, uint32_t b0, uint32_t b1){
    asm volatile(
      "mma.sync.aligned.m16n8k8.row.col.f32.tf32.tf32.f32 "
      "{%0,%1,%2,%3}, {%4,%5,%6,%7}, {%8,%9}, {%0,%1,%2,%3};"
      : "+f"(c[0]),"+f"(c[1]),"+f"(c[2]),"+f"(c[3])
      : "r"(a[0]),"r"(a[1]),"r"(a[2]),"r"(a[3]), "r"(b0),"r"(b1));
}

// ---------------------------------------------------------------------------
// Per-node GEMM with 3xTF32 split (fp32 accuracy on tensor pipe):
//   out[(n*Bb+b)*OS + o_off+o] = bias[n*O_w+o] + sum_k A1*W1 (+ A2*W2)
// A node-major: A[(n*Bb+b)*K + k];  W: W[(n*K+k)*O_w + o]
// grid = (NN, O_w/128, Bb/64), 256 thr. Block tile 64(M)x128(N), k-chunk 16.
// 8 warps as 2(M)x4(N); warp tile 32x32 (2 m-tiles x 4 n-tiles of m16n8k8).
// ---------------------------------------------------------------------------
#define SA 72    // 64 + 8 pad  -> bank (8*k + m) conflict-free frag loads
#define SW 136   // 128 + 8 pad

__global__ void __launch_bounds__(256,2) gemm_tf32(
    const float* __restrict__ A1, int K1,
    const float* __restrict__ A2, int K2,
    const float* __restrict__ W1, const float* __restrict__ W2,
    const float* __restrict__ bias,
    int O_w, int OS, int o_off, float* __restrict__ out)
{
    __shared__ float sAhi[16*SA], sAlo[16*SA];
    __shared__ float sWhi[16*SW], sWlo[16*SW];

    const int n  = blockIdx.x;
    const int o0 = blockIdx.y << 7;
    const int b0 = blockIdx.z << 6;
    const int t  = threadIdx.x, lane = t & 31, w = t >> 5;
    const int wM = (w >> 2) << 5;     // 0 / 32
    const int wN = (w & 3)  << 5;     // 0..96
    const int g  = lane >> 2, t4 = lane & 3;

    const int ar  = t >> 2, ac4 = t & 3;     // A loader: row, float4 col
    const int wk  = t >> 4, wo4 = t & 15;    // W loader: k row, float4 col

    float acc[2][4][4];
    #pragma unroll
    for (int mt=0;mt<2;mt++)
        #pragma unroll
        for (int nt=0;nt<4;nt++)
            #pragma unroll
            for (int j=0;j<4;j++) acc[mt][nt][j]=0.f;

    #pragma unroll 1
    for (int ph=0; ph<2; ph++){
        const float* Ap = ph ? A2 : A1;
        const float* Wp = ph ? W2 : W1;
        const int K = ph ? K2 : K1;
        if (K <= 0) continue;
        #pragma unroll 1
        for (int k0=0; k0<K; k0+=16){
            const int kc = min(16, K-k0);
            __syncthreads();
            // ---- stage A (64 x kc), split hi/lo, store k-major ----
            if (ac4*4 < kc){
                float4 v = *(const float4*)&Ap[((long)n*Bb + b0 + ar)*K + k0 + ac4*4];
                float f[4] = {v.x,v.y,v.z,v.w};
                #pragma unroll
                for (int j=0;j<4;j++){
                    uint32_t hb = f2tf32(f[j]);
                    float lo = f[j] - __uint_as_float(hb);
                    sAhi[(ac4*4+j)*SA + ar] = __uint_as_float(hb);
                    sAlo[(ac4*4+j)*SA + ar] = __uint_as_float(f2tf32(lo));
                }
            }
            // ---- stage W (kc x 128), split hi/lo ----
            #pragma unroll
            for (int rep=0; rep<2; rep++){
                const int o4 = wo4 + rep*16;
                if (wk < kc){
                    float4 v = *(const float4*)&Wp[((long)n*K + k0 + wk)*O_w + o0 + o4*4];
                    float f[4] = {v.x,v.y,v.z,v.w};
                    float h4[4], l4[4];
                    #pragma unroll
                    for (int j=0;j<4;j++){
                        uint32_t hb = f2tf32(f[j]);
                        h4[j] = __uint_as_float(hb);
                        l4[j] = __uint_as_float(f2tf32(f[j] - h4[j]));
                    }
                    *(float4*)&sWhi[wk*SW + o4*4] = make_float4(h4[0],h4[1],h4[2],h4[3]);
                    *(float4*)&sWlo[wk*SW + o4*4] = make_float4(l4[0],l4[1],l4[2],l4[3]);
                }
            }
            __syncthreads();
            // ---- compute ----
            const int steps = kc >> 3;
            #pragma unroll
            for (int s=0; s<2; s++){
                if (s >= steps) break;
                uint32_t ah[2][4], al[2][4];
                const float* pa  = &sAhi[(s*8 + t4)*SA + wM + g];
                const float* pal = &sAlo[(s*8 + t4)*SA + wM + g];
                #pragma unroll
                for (int mt=0;mt<2;mt++){
                    ah[mt][0]=__float_as_uint(pa [mt*16]);
                    ah[mt][1]=__float_as_uint(pa [mt*16+8]);
                    ah[mt][2]=__float_as_uint(pa [4*SA+mt*16]);
                    ah[mt][3]=__float_as_uint(pa [4*SA+mt*16+8]);
                    al[mt][0]=__float_as_uint(pal[mt*16]);
                    al[mt][1]=__float_as_uint(pal[mt*16+8]);
                    al[mt][2]=__float_as_uint(pal[4*SA+mt*16]);
                    al[mt][3]=__float_as_uint(pal[4*SA+mt*16+8]);
                }
                #pragma unroll
                for (int nt=0;nt<4;nt++){
                    const float* pw  = &sWhi[(s*8 + t4)*SW + wN + nt*8 + g];
                    const float* pwl = &sWlo[(s*8 + t4)*SW + wN + nt*8 + g];
                    uint32_t bh0 = __float_as_uint(pw [0]);
                    uint32_t bh1 = __float_as_uint(pw [4*SW]);
                    uint32_t bl0 = __float_as_uint(pwl[0]);
                    uint32_t bl1 = __float_as_uint(pwl[4*SW]);
                    #pragma unroll
                    for (int mt=0;mt<2;mt++) mma8(acc[mt][nt], ah[mt], bh0, bh1);
                    #pragma unroll
                    for (int mt=0;mt<2;mt++) mma8(acc[mt][nt], al[mt], bh0, bh1);
                    #pragma unroll
                    for (int mt=0;mt<2;mt++) mma8(acc[mt][nt], ah[mt], bl0, bl1);
                }
            }
        }
    }
    // ---- epilogue: bias + store (c0,c1)/(c2,c3) as float2 ----
    #pragma unroll
    for (int mt=0;mt<2;mt++){
        const int r0 = b0 + wM + mt*16 + g;
        #pragma unroll
        for (int nt=0;nt<4;nt++){
            const int oc = o0 + wN + nt*8 + t4*2;
            const float bv0 = bias[n*O_w + oc];
            const float bv1 = bias[n*O_w + oc + 1];
            const int col = o_off + oc;
            long base0 = ((long)n*Bb + r0    )*OS + col;
            long base1 = ((long)n*Bb + r0 + 8)*OS + col;
            *(float2*)&out[base0] = make_float2(acc[mt][nt][0]+bv0, acc[mt][nt][1]+bv1);
            *(float2*)&out[base1] = make_float2(acc[mt][nt][2]+bv0, acc[mt][nt][3]+bv1);
        }
    }
}

// ---------------------------------------------------------------------------
// G-mix + LSTM cell. gates node-major: gates[(n*Bb+b)*512 + ...]
// grid (Bb, 4): block handles batch b, 32 gate-channels (x4 gate groups).
// 128 threads; smem 14.6KB -> high occupancy.
// ---------------------------------------------------------------------------
__global__ void __launch_bounds__(128) lstm_mix(
    const float* __restrict__ gates, const float* __restrict__ G,
    const float* __restrict__ c_in,
    float* __restrict__ h_out, float* __restrict__ c_out,
    float* __restrict__ yi_out)
{
    __shared__ float sGt[NN*128];   // [n][grp*32 + c]
    __shared__ float sGm[NN*NN];

    const int b = blockIdx.x, cb = blockIdx.y, c0 = cb*32;
    const int t = threadIdx.x;

    for (int i=t; i<NN*4*8; i+=128){
        int f4 = i & 7, grp = (i>>3)&3, n = i>>5;
        float4 v = *(const float4*)&gates[((long)n*Bb + b)*512 + grp*128 + c0 + f4*4];
        *(float4*)&sGt[n*128 + grp*32 + f4*4] = v;
    }
    for (int i=t; i<NN*NN; i+=128) sGm[i] = G[i];
    __syncthreads();

    const int c = t & 31, mg = t >> 5;   // mg: 0..3, each 6 m
    float acc[6][4];
    #pragma unroll
    for (int mm=0;mm<6;mm++)
        #pragma unroll
        for (int j=0;j<4;j++) acc[mm][j]=0.f;

    #pragma unroll 4
    for (int n=0;n<NN;n++){
        float vi = sGt[n*128 +      c];
        float vf = sGt[n*128 + 32 + c];
        float vg = sGt[n*128 + 64 + c];
        float vo = sGt[n*128 + 96 + c];
        #pragma unroll
        for (int mm=0;mm<6;mm++){
            float gm = sGm[(mg*6+mm)*NN + n];
            acc[mm][0] = fmaf(gm, vi, acc[mm][0]);
            acc[mm][1] = fmaf(gm, vf, acc[mm][1]);
            acc[mm][2] = fmaf(gm, vg, acc[mm][2]);
            acc[mm][3] = fmaf(gm, vo, acc[mm][3]);
        }
    }
    #pragma unroll
    for (int mm=0;mm<6;mm++){
        const int m = mg*6+mm;
        const long idx = ((long)m*Bb + b)*128 + c0 + c;
        float cold = c_in[idx];
        float cn = sigf(acc[mm][1])*cold + sigf(acc[mm][0])*tanhacc(acc[mm][2]);
        float hn = sigf(acc[mm][3])*tanhacc(cn);
        c_out[idx] = cn;
        h_out[idx] = hn;
        if (yi_out) yi_out[idx] = tanhacc(hn);
    }
}

// ---------------------------------------------------------------------------
// Head (fcpre node-major now). block per batch b, 256 threads.
// ---------------------------------------------------------------------------
__global__ void __launch_bounds__(256) head_kernel(
    const float* __restrict__ G,
    const float* __restrict__ locW, const float* __restrict__ locB,
    const float* __restrict__ lzW,  const float* __restrict__ lzB,
    float* __restrict__ out, int tstep)
{
    extern __shared__ float smem[];
    float* sP  = smem;                 // NN*256
    float* sY  = sP  + NN*256;         // NN*256
    float* sG  = sY  + NN*256;         // NN*NN
    float* sQ  = sG  + NN*NN;          // NN*8
    float* sLW = sQ  + NN*8;           // 384
    float* sLZ = sLW + 128*3;          // 512

    const int b = blockIdx.x, t = threadIdx.x;
    for (int i=t;i<NN*256;i+=256){
        int n = i>>8, f = i&255;
        sP[i] = g_fcpre[((long)n*Bb + b)*256 + f];
    }
    for (int i=t;i<NN*NN;i+=256)  sG[i]=G[i];
    for (int i=t;i<384;i+=256)    sLW[i]=locW[i];
    for (int i=t;i<512;i+=256)    sLZ[i]=lzW[i];
    __syncthreads();

    {
        const int ocg = t & 63;
        const int mg  = t >> 6;
        const float4* p4 = (const float4*)sP;
        float acc[6][4];
        #pragma unroll
        for (int mm=0;mm<6;mm++)
            #pragma unroll
            for (int j=0;j<4;j++) acc[mm][j]=0.f;
        #pragma unroll 4
        for (int n=0;n<NN;n++){
            float4 v = p4[n*64 + ocg];
            #pragma unroll
            for (int mm=0;mm<6;mm++){
                float gm = sG[(mg*6+mm)*NN + n];
                acc[mm][0]=fmaf(gm,v.x,acc[mm][0]); acc[mm][1]=fmaf(gm,v.y,acc[mm][1]);
                acc[mm][2]=fmaf(gm,v.z,acc[mm][2]); acc[mm][3]=fmaf(gm,v.w,acc[mm][3]);
            }
        }
        #pragma unroll
        for (int mm=0;mm<6;mm++){
            int m = mg*6+mm;
            *(float4*)&sY[m*256 + ocg*4] =
                make_float4(tanhacc(acc[mm][0]),tanhacc(acc[mm][1]),
                            tanhacc(acc[mm][2]),tanhacc(acc[mm][3]));
        }
    }
    __syncthreads();

    if (t < NN*7){
        int n = t/7, j = t%7;
        float a;
        if (j < 3){
            a = locB[j];
            #pragma unroll 8
            for (int f=0;f<128;f++) a = fmaf(sY[n*256+f], sLW[f*3+j], a);
        } else {
            int j2 = j-3;
            a = lzB[j2];
            #pragma unroll 8
            for (int f=0;f<128;f++) a = fmaf(sY[n*256+128+f], sLZ[f*4+j2], a);
        }
        sQ[n*8+j] = a;
    }
    __syncthreads();

    if (t < NN){
        int m = t;
        float s[7];
        #pragma unroll
        for (int j=0;j<7;j++){
            float a = 0.f;
            #pragma unroll 4
            for (int n=0;n<NN;n++) a = fmaf(sG[m*NN+n], sQ[n*8+j], a);
            s[j]=a;
        }
        float inv = rsqrtf(1.0f + s[0]*s[0] + s[1]*s[1] + s[2]*s[2]);
        float dw=inv, dx=s[0]*inv, dy=s[1]*inv, dz=s[2]*inv;
        long bm = (long)b*NN + m;
        float qw=g_locstart[bm*4+0], qx=g_locstart[bm*4+1],
              qy=g_locstart[bm*4+2], qz=g_locstart[bm*4+3];
        float lw = qw*dw - qx*dx - qy*dy - qz*dz;
        float lx = qw*dx + qx*dw + qy*dz - qz*dy;
        float ly = qw*dy - qx*dz + qy*dw + qz*dx;
        float lz = qw*dz + qx*dy - qy*dx + qz*dw;
        g_locstart[bm*4+0]=lw; g_locstart[bm*4+1]=lx;
        g_locstart[bm*4+2]=ly; g_locstart[bm*4+3]=lz;

        long oo = (((long)b*TT + tstep)*NN + m)*4;
        out[oo+0]=lw; out[oo+1]=lx; out[oo+2]=ly; out[oo+3]=lz;
        long oz = (long)Bb*TT*NN*4 + oo;
        out[oz+0]=s[3]; out[oz+1]=s[4]; out[oz+2]=s[5]; out[oz+3]=s[6];

        float* xi = &g_xi[((long)m*Bb + b)*72 + 64];
        xi[0]=lw; xi[1]=lx; xi[2]=ly; xi[3]=lz;
        xi[4]=dw; xi[5]=dx; xi[6]=dy; xi[7]=dz;
    }
}

// ---------------------------------------------------------------------------
// init: h0/c0 = G @ (enc @ ihW + ihb) ; node-major outputs
// ---------------------------------------------------------------------------
__global__ void __launch_bounds__(256) init_state(
    const float* __restrict__ enc, const float* __restrict__ G,
    const float* __restrict__ W1, const float* __restrict__ b1,
    const float* __restrict__ W2, const float* __restrict__ b2)
{
    extern __shared__ float smem[];
    float* sE  = smem;             // NN*256
    float* sY1 = sE  + NN*256;     // NN*128
    float* sY2 = sY1 + NN*128;     // NN*128
    float* sG  = sY2 + NN*128;     // NN*NN

    const int b = blockIdx.x, t = threadIdx.x;
    const float* eb = enc + (long)b*NN*256;
    for (int i=t;i<NN*256;i+=256) sE[i]=eb[i];
    for (int i=t;i<NN*NN;i+=256)  sG[i]=G[i];
    __syncthreads();
    for (int idx=t; idx<NN*128; idx+=256){
        int n = idx>>7, o = idx&127;
        float a1 = b1[o], a2 = b2[o];
        for (int h=0; h<256; h++){
            float e = sE[n*256+h];
            a1 = fmaf(e, W1[h*128+o], a1);
            a2 = fmaf(e, W2[h*128+o], a2);
        }
        sY1[idx]=a1; sY2[idx]=a2;
    }
    __syncthreads();
    for (int idx=t; idx<NN*128; idx+=256){
        int m = idx>>7, o = idx&127;
        float h0=0.f, c0=0.f;
        #pragma unroll 4
        for (int n=0;n<NN;n++){
            float gm = sG[m*NN+n];
            h0 = fmaf(gm, sY1[n*128+o], h0);
            c0 = fmaf(gm, sY2[n*128+o], c0);
        }
        long off = ((long)m*Bb + b)*128 + o;
        g_h1[off]=h0; g_c1[off]=c0; g_h2[off]=h0; g_c2[off]=c0;
    }
}

__global__ void init_xi(const float* __restrict__ x, const float* __restrict__ z)
{
    int i = blockIdx.x*blockDim.x + threadIdx.x;
    if (i < NN*Bb*72){
        int f = i % 72, nb = i / 72;
        int b = nb % Bb, n = nb / Bb;
        g_xi[i] = (f < 64) ? z[(b*NN + n)*64 + f] : x[(b*NN + n)*8 + (f-64)];
    }
    if (i < Bb*NN*4){
        int j = i % 4, bn = i / 4;
        g_locstart[i] = x[bn*8 + j];
    }
}

// ---------------------------------------------------------------------------
extern "C" void kernel_launch(void* const* d_in, const int* in_sizes, int n_in,
                              void* d_out, int out_size)
{
    const float* x    = (const float*)d_in[0];
    const float* enc  = (const float*)d_in[1];
    const float* z    = (const float*)d_in[2];
    const float* G    = (const float*)d_in[4];
    const float* Wx0  = (const float*)d_in[5];
    const float* Wh0  = (const float*)d_in[6];
    const float* b0_  = (const float*)d_in[7];
    const float* Wx1  = (const float*)d_in[8];
    const float* Wh1  = (const float*)d_in[9];
    const float* b1_  = (const float*)d_in[10];
    const float* fcW  = (const float*)d_in[11];
    const float* fcB  = (const float*)d_in[12];
    const float* fc2W = (const float*)d_in[13];
    const float* fc2B = (const float*)d_in[14];
    const float* ih1W = (const float*)d_in[15];
    const float* ih1B = (const float*)d_in[16];
    const float* ih2W = (const float*)d_in[17];
    const float* ih2B = (const float*)d_in[18];
    const float* locW = (const float*)d_in[19];
    const float* locB = (const float*)d_in[20];
    const float* lzW  = (const float*)d_in[21];
    const float* lzB  = (const float*)d_in[22];
    float* out = (float*)d_out;

    float *p_xi,*p_h1,*p_c1,*p_h2,*p_c2,*p_yi,*p_gates,*p_fcpre;
    cudaGetSymbolAddress((void**)&p_xi, g_xi);
    cudaGetSymbolAddress((void**)&p_h1, g_h1);
    cudaGetSymbolAddress((void**)&p_c1, g_c1);
    cudaGetSymbolAddress((void**)&p_h2, g_h2);
    cudaGetSymbolAddress((void**)&p_c2, g_c2);
    cudaGetSymbolAddress((void**)&p_yi, g_yi);
    cudaGetSymbolAddress((void**)&p_gates, g_gates);
    cudaGetSymbolAddress((void**)&p_fcpre, g_fcpre);

    const int smem_head = (NN*256 + NN*256 + NN*NN + NN*8 + 128*3 + 128*4)*4;
    const int smem_init = (NN*256 + NN*128 + NN*128 + NN*NN)*4;
    cudaFuncSetAttribute(head_kernel,cudaFuncAttributeMaxDynamicSharedMemorySize, smem_head);
    cudaFuncSetAttribute(init_state, cudaFuncAttributeMaxDynamicSharedMemorySize, smem_init);

    init_state<<<Bb, 256, smem_init>>>(enc, G, ih1W, ih1B, ih2W, ih2B);
    init_xi<<<(NN*Bb*72 + 255)/256, 256>>>(x, z);

    dim3 gl(NN, 4, Bb/64);   // lstm gemms: O_w=512
    dim3 gf(NN, 1, Bb/64);   // fc gemms:  O_w=128
    dim3 gm(Bb, 4);          // lstm_mix

    for (int t = 0; t < TT; t++){
        gemm_tf32<<<gl, 256>>>(p_xi, 72,  p_h1, 128, Wx0, Wh0, b0_, 512, 512, 0, p_gates);
        lstm_mix <<<gm, 128>>>(p_gates, G, p_c1, p_h1, p_c1, nullptr);
        gemm_tf32<<<gl, 256>>>(p_h1, 128, p_h2, 128, Wx1, Wh1, b1_, 512, 512, 0, p_gates);
        lstm_mix <<<gm, 128>>>(p_gates, G, p_c2, p_h2, p_c2, p_yi);
        gemm_tf32<<<gf, 256>>>(p_yi, 128, nullptr, 0, fcW,  nullptr, fcB,  128, 256, 0,   p_fcpre);
        gemm_tf32<<<gf, 256>>>(p_yi, 128, nullptr, 0, fc2W, nullptr, fc2B, 128, 256, 128, p_fcpre);
        head_kernel<<<Bb, 256, smem_head>>>(G, locW, locB, lzW, lzB, out, t);
    }
}

// round 3
// speedup vs baseline: 1.7973x; 1.5413x over previous
#include <cuda_runtime.h>
#include <cuda_fp16.h>
#include <cstdint>

#define Bb   512
#define NN   24
#define TT   25

// ---------------- scratch (device globals) ----------------
// activations node-major: X[(n*Bb + b)*F + f], stored as fp16 hi/lo pairs
__device__ half  g_xiH[NN*Bb*80],  g_xiL[NN*Bb*80];     // xi padded 72->80
__device__ half  g_h1H[NN*Bb*128], g_h1L[NN*Bb*128];
__device__ half  g_h2H[NN*Bb*128], g_h2L[NN*Bb*128];
__device__ half  g_yiH[NN*Bb*128], g_yiL[NN*Bb*128];
__device__ float g_c1[NN*Bb*128], g_c2[NN*Bb*128];
__device__ float g_gates[NN*Bb*512];
__device__ float g_fcpre[NN*Bb*256];
__device__ float g_locstart[Bb*NN*4];

// prepacked weights (hi/lo fp16), concatenated K:
__device__ half g_w0H[NN*208*512], g_w0L[NN*208*512];   // [xi(80 pad) ; Wh0(128)]
__device__ half g_w1H[NN*256*512], g_w1L[NN*256*512];   // [Wx1 ; Wh1]
__device__ half g_wfH[NN*128*256], g_wfL[NN*128*256];   // fcW cols 0-127, fc2W 128-255
__device__ float g_fcBc[NN*256];

// ---------------- activations ----------------
__device__ __forceinline__ float sigf(float x){ return 1.0f/(1.0f+__expf(-x)); }
__device__ __forceinline__ float tanhacc(float x){
    float ax = fabsf(x);
    float e  = __expf(-2.0f*ax);
    float t  = (1.0f - e)/(1.0f + e);
    return copysignf(t, x);
}
__device__ __forceinline__ void splitH(float x, half& h, half& l){
    h = __float2half_rn(x);
    l = __float2half_rn(x - __half2float(h));
}

// ---------------- mma helpers ----------------
__device__ __forceinline__ uint32_t sptr(const void* p){
    return (uint32_t)__cvta_generic_to_shared(p);
}
__device__ __forceinline__ void ldm4(uint32_t* r, const half* p){
    asm volatile("ldmatrix.sync.aligned.m8n8.x4.shared.b16 {%0,%1,%2,%3},[%4];"
        : "=r"(r[0]),"=r"(r[1]),"=r"(r[2]),"=r"(r[3]) : "r"(sptr(p)));
}
__device__ __forceinline__ void ldm4t(uint32_t* r, const half* p){
    asm volatile("ldmatrix.sync.aligned.m8n8.x4.trans.shared.b16 {%0,%1,%2,%3},[%4];"
        : "=r"(r[0]),"=r"(r[1]),"=r"(r[2]),"=r"(r[3]) : "r"(sptr(p)));
}
__device__ __forceinline__ void mma16(float* c, const uint32_t* a, const uint32_t* b){
    asm volatile(
      "mma.sync.aligned.m16n8k16.row.col.f32.f16.f16.f32 "
      "{%0,%1,%2,%3},{%4,%5,%6,%7},{%8,%9},{%0,%1,%2,%3};"
      : "+f"(c[0]),"+f"(c[1]),"+f"(c[2]),"+f"(c[3])
      : "r"(a[0]),"r"(a[1]),"r"(a[2]),"r"(a[3]),"r"(b[0]),"r"(b[1]));
}

// ---------------------------------------------------------------------------
// Per-node fp16-split GEMM:
//   out[(n*Bb+b)*O_w + o] = bias[n*O_w+o] + A1*W[0:K1] + A2*W[K1:K1+K2]
// A: node-major halves (hi/lo), stride sA;  W: prepacked concat halves.
// grid (NN, O_w/128, Bb/64), 256 thr. Tile 64x128, k-chunk 16.
// 8 warps = 2(M)x4(N); warp 32x32; 3-product hi/lo split => fp32-class accuracy.
// ---------------------------------------------------------------------------
#define SAS 24     // A smem stride (16+8 halves)  -> ldmatrix conflict-free
#define SWS 136    // W smem stride (128+8 halves) -> ldmatrix conflict-free

__global__ void __launch_bounds__(256) gemm_fp16(
    const half* __restrict__ AH1, const half* __restrict__ AL1, int kc1, int sA1,
    const half* __restrict__ AH2, const half* __restrict__ AL2, int kc2, int sA2,
    const half* __restrict__ WH,  const half* __restrict__ WL,  int Kw,
    const float* __restrict__ bias, int O_w, float* __restrict__ out)
{
    __shared__ half sAh[64*SAS], sAl[64*SAS];
    __shared__ half sWh[16*SWS], sWl[16*SWS];

    const int n  = blockIdx.x;
    const int o0 = blockIdx.y << 7;
    const int b0 = blockIdx.z << 6;
    const int t  = threadIdx.x, lane = t & 31, w = t >> 5;
    const int wM = (w >> 2) << 5;       // 0 / 32
    const int wN = (w & 3)  << 5;       // 0..96
    const int g  = lane >> 2, t4 = lane & 3;

    // fragment smem offsets (halves)
    const int aoff = (lane & 15)*SAS + (lane >> 4)*8;
    const int boff = (lane & 15)*SWS + wN + (lane >> 4)*8;

    // W loader
    const int wrow = t >> 4, wc16 = t & 15;
    // A loader (128 threads hi, 128 lo)
    const int tt = t & 127, arow = tt >> 1, achk = tt & 1;

    float acc[2][4][4];
    #pragma unroll
    for (int mt=0;mt<2;mt++)
        #pragma unroll
        for (int nt=0;nt<4;nt++)
            #pragma unroll
            for (int j=0;j<4;j++) acc[mt][nt][j]=0.f;

    const int total = kc1 + kc2;
    #pragma unroll 1
    for (int c=0; c<total; c++){
        const half* pA = (c < kc1) ? (t < 128 ? AH1 : AL1) : (t < 128 ? AH2 : AL2);
        const int   sA = (c < kc1) ? sA1 : sA2;
        const int   k0 = (c < kc1) ? c*16 : (c-kc1)*16;
        __syncthreads();
        // ---- stage A (64 x 16 halves, hi & lo) ----
        {
            long gi = ((long)n*Bb + b0 + arow)*sA + k0 + achk*8;
            half* dst = (t < 128 ? sAh : sAl) + arow*SAS + achk*8;
            *(uint4*)dst = *(const uint4*)&pA[gi];
        }
        // ---- stage W (16 x 128 halves, hi & lo) ----
        {
            long gi = ((long)n*Kw + c*16 + wrow)*O_w + o0 + wc16*8;
            *(uint4*)&sWh[wrow*SWS + wc16*8] = *(const uint4*)&WH[gi];
            *(uint4*)&sWl[wrow*SWS + wc16*8] = *(const uint4*)&WL[gi];
        }
        __syncthreads();
        // ---- fragments ----
        uint32_t ah[2][4], al[2][4];
        #pragma unroll
        for (int mt=0;mt<2;mt++){
            ldm4(ah[mt], &sAh[(wM + mt*16)*SAS + aoff]);
            ldm4(al[mt], &sAl[(wM + mt*16)*SAS + aoff]);
        }
        uint32_t bh[4][2], bl[4][2];
        #pragma unroll
        for (int p=0;p<2;p++){
            uint32_t r[4];
            ldm4t(r, &sWh[boff + p*16]);
            bh[2*p][0]=r[0]; bh[2*p][1]=r[1]; bh[2*p+1][0]=r[2]; bh[2*p+1][1]=r[3];
            ldm4t(r, &sWl[boff + p*16]);
            bl[2*p][0]=r[0]; bl[2*p][1]=r[1]; bl[2*p+1][0]=r[2]; bl[2*p+1][1]=r[3];
        }
        // ---- 3-product split MMAs ----
        #pragma unroll
        for (int nt=0;nt<4;nt++){
            #pragma unroll
            for (int mt=0;mt<2;mt++){
                mma16(acc[mt][nt], ah[mt], bh[nt]);
                mma16(acc[mt][nt], ah[mt], bl[nt]);
                mma16(acc[mt][nt], al[mt], bh[nt]);
            }
        }
    }
    // ---- epilogue: bias + store ----
    #pragma unroll
    for (int mt=0;mt<2;mt++){
        const int r0 = b0 + wM + mt*16 + g;
        #pragma unroll
        for (int nt=0;nt<4;nt++){
            const int oc = o0 + wN + nt*8 + t4*2;
            const float bv0 = bias[n*O_w + oc];
            const float bv1 = bias[n*O_w + oc + 1];
            long base0 = ((long)n*Bb + r0    )*O_w + oc;
            long base1 = ((long)n*Bb + r0 + 8)*O_w + oc;
            *(float2*)&out[base0] = make_float2(acc[mt][nt][0]+bv0, acc[mt][nt][1]+bv1);
            *(float2*)&out[base1] = make_float2(acc[mt][nt][2]+bv0, acc[mt][nt][3]+bv1);
        }
    }
}

// ---------------------------------------------------------------------------
// G-mix + LSTM cell. h written as fp16 hi/lo (GEMM input); c fp32.
// grid (Bb, 4) x 128 threads.
// ---------------------------------------------------------------------------
__global__ void __launch_bounds__(128) lstm_mix(
    const float* __restrict__ gates, const float* __restrict__ G,
    const float* __restrict__ c_in,  float* __restrict__ c_out,
    half* __restrict__ hH, half* __restrict__ hL,
    half* __restrict__ yiH, half* __restrict__ yiL)
{
    __shared__ float sGt[NN*128];
    __shared__ float sGm[NN*NN];

    const int b = blockIdx.x, c0 = blockIdx.y*32;
    const int t = threadIdx.x;

    for (int i=t; i<NN*4*8; i+=128){
        int f4 = i & 7, grp = (i>>3)&3, n = i>>5;
        float4 v = *(const float4*)&gates[((long)n*Bb + b)*512 + grp*128 + c0 + f4*4];
        *(float4*)&sGt[n*128 + grp*32 + f4*4] = v;
    }
    for (int i=t; i<NN*NN; i+=128) sGm[i] = G[i];
    __syncthreads();

    const int c = t & 31, mg = t >> 5;
    float acc[6][4];
    #pragma unroll
    for (int mm=0;mm<6;mm++)
        #pragma unroll
        for (int j=0;j<4;j++) acc[mm][j]=0.f;

    #pragma unroll 4
    for (int n=0;n<NN;n++){
        float vi = sGt[n*128 +      c];
        float vf = sGt[n*128 + 32 + c];
        float vg = sGt[n*128 + 64 + c];
        float vo = sGt[n*128 + 96 + c];
        #pragma unroll
        for (int mm=0;mm<6;mm++){
            float gm = sGm[(mg*6+mm)*NN + n];
            acc[mm][0] = fmaf(gm, vi, acc[mm][0]);
            acc[mm][1] = fmaf(gm, vf, acc[mm][1]);
            acc[mm][2] = fmaf(gm, vg, acc[mm][2]);
            acc[mm][3] = fmaf(gm, vo, acc[mm][3]);
        }
    }
    #pragma unroll
    for (int mm=0;mm<6;mm++){
        const int m = mg*6+mm;
        const long idx = ((long)m*Bb + b)*128 + c0 + c;
        float cold = c_in[idx];
        float cn = sigf(acc[mm][1])*cold + sigf(acc[mm][0])*tanhacc(acc[mm][2]);
        float hn = sigf(acc[mm][3])*tanhacc(cn);
        c_out[idx] = cn;
        half h,l; splitH(hn, h, l);
        hH[idx]=h; hL[idx]=l;
        if (yiH){
            float y = tanhacc(hn);
            splitH(y, h, l);
            yiH[idx]=h; yiL[idx]=l;
        }
    }
}

// ---------------------------------------------------------------------------
// Head: tanh(Gmix(fcpre)) -> small projections -> Gmix -> quat -> outputs.
// ---------------------------------------------------------------------------
__global__ void __launch_bounds__(256) head_kernel(
    const float* __restrict__ G,
    const float* __restrict__ locW, const float* __restrict__ locB,
    const float* __restrict__ lzW,  const float* __restrict__ lzB,
    float* __restrict__ out, int tstep)
{
    extern __shared__ float smem[];
    float* sP  = smem;                 // NN*256
    float* sY  = sP  + NN*256;         // NN*256
    float* sG  = sY  + NN*256;         // NN*NN
    float* sQ  = sG  + NN*NN;          // NN*8
    float* sLW = sQ  + NN*8;           // 384
    float* sLZ = sLW + 128*3;          // 512

    const int b = blockIdx.x, t = threadIdx.x;
    for (int i=t;i<NN*256;i+=256){
        int n = i>>8, f = i&255;
        sP[i] = g_fcpre[((long)n*Bb + b)*256 + f];
    }
    for (int i=t;i<NN*NN;i+=256)  sG[i]=G[i];
    for (int i=t;i<384;i+=256)    sLW[i]=locW[i];
    for (int i=t;i<512;i+=256)    sLZ[i]=lzW[i];
    __syncthreads();

    {
        const int ocg = t & 63;
        const int mg  = t >> 6;
        const float4* p4 = (const float4*)sP;
        float acc[6][4];
        #pragma unroll
        for (int mm=0;mm<6;mm++)
            #pragma unroll
            for (int j=0;j<4;j++) acc[mm][j]=0.f;
        #pragma unroll 4
        for (int n=0;n<NN;n++){
            float4 v = p4[n*64 + ocg];
            #pragma unroll
            for (int mm=0;mm<6;mm++){
                float gm = sG[(mg*6+mm)*NN + n];
                acc[mm][0]=fmaf(gm,v.x,acc[mm][0]); acc[mm][1]=fmaf(gm,v.y,acc[mm][1]);
                acc[mm][2]=fmaf(gm,v.z,acc[mm][2]); acc[mm][3]=fmaf(gm,v.w,acc[mm][3]);
            }
        }
        #pragma unroll
        for (int mm=0;mm<6;mm++){
            int m = mg*6+mm;
            *(float4*)&sY[m*256 + ocg*4] =
                make_float4(tanhacc(acc[mm][0]),tanhacc(acc[mm][1]),
                            tanhacc(acc[mm][2]),tanhacc(acc[mm][3]));
        }
    }
    __syncthreads();

    if (t < NN*7){
        int n = t/7, j = t%7;
        float a;
        if (j < 3){
            a = locB[j];
            #pragma unroll 8
            for (int f=0;f<128;f++) a = fmaf(sY[n*256+f], sLW[f*3+j], a);
        } else {
            int j2 = j-3;
            a = lzB[j2];
            #pragma unroll 8
            for (int f=0;f<128;f++) a = fmaf(sY[n*256+128+f], sLZ[f*4+j2], a);
        }
        sQ[n*8+j] = a;
    }
    __syncthreads();

    if (t < NN){
        int m = t;
        float s[7];
        #pragma unroll
        for (int j=0;j<7;j++){
            float a = 0.f;
            #pragma unroll 4
            for (int n=0;n<NN;n++) a = fmaf(sG[m*NN+n], sQ[n*8+j], a);
            s[j]=a;
        }
        float inv = rsqrtf(1.0f + s[0]*s[0] + s[1]*s[1] + s[2]*s[2]);
        float dw=inv, dx=s[0]*inv, dy=s[1]*inv, dz=s[2]*inv;
        long bm = (long)b*NN + m;
        float qw=g_locstart[bm*4+0], qx=g_locstart[bm*4+1],
              qy=g_locstart[bm*4+2], qz=g_locstart[bm*4+3];
        float lw = qw*dw - qx*dx - qy*dy - qz*dz;
        float lx = qw*dx + qx*dw + qy*dz - qz*dy;
        float ly = qw*dy - qx*dz + qy*dw + qz*dx;
        float lz = qw*dz + qx*dy - qy*dx + qz*dw;
        g_locstart[bm*4+0]=lw; g_locstart[bm*4+1]=lx;
        g_locstart[bm*4+2]=ly; g_locstart[bm*4+3]=lz;

        long oo = (((long)b*TT + tstep)*NN + m)*4;
        out[oo+0]=lw; out[oo+1]=lx; out[oo+2]=ly; out[oo+3]=lz;
        long oz = (long)Bb*TT*NN*4 + oo;
        out[oz+0]=s[3]; out[oz+1]=s[4]; out[oz+2]=s[5]; out[oz+3]=s[6];

        // rebuild xi[64:72] halves
        long xb = ((long)m*Bb + b)*80 + 64;
        float xv[8] = {lw,lx,ly,lz,dw,dx,dy,dz};
        #pragma unroll
        for (int j=0;j<8;j++){
            half h,l; splitH(xv[j], h, l);
            g_xiH[xb+j]=h; g_xiL[xb+j]=l;
        }
    }
}

// ---------------------------------------------------------------------------
// init: h0/c0 = G @ (enc @ ihW + ihb) ; writes fp16 h, fp32 c
// ---------------------------------------------------------------------------
__global__ void __launch_bounds__(256) init_state(
    const float* __restrict__ enc, const float* __restrict__ G,
    const float* __restrict__ W1, const float* __restrict__ b1,
    const float* __restrict__ W2, const float* __restrict__ b2)
{
    extern __shared__ float smem[];
    float* sE  = smem;             // NN*256
    float* sY1 = sE  + NN*256;     // NN*128
    float* sY2 = sY1 + NN*128;     // NN*128
    float* sG  = sY2 + NN*128;     // NN*NN

    const int b = blockIdx.x, t = threadIdx.x;
    const float* eb = enc + (long)b*NN*256;
    for (int i=t;i<NN*256;i+=256) sE[i]=eb[i];
    for (int i=t;i<NN*NN;i+=256)  sG[i]=G[i];
    __syncthreads();
    for (int idx=t; idx<NN*128; idx+=256){
        int n = idx>>7, o = idx&127;
        float a1 = b1[o], a2 = b2[o];
        for (int h=0; h<256; h++){
            float e = sE[n*256+h];
            a1 = fmaf(e, W1[h*128+o], a1);
            a2 = fmaf(e, W2[h*128+o], a2);
        }
        sY1[idx]=a1; sY2[idx]=a2;
    }
    __syncthreads();
    for (int idx=t; idx<NN*128; idx+=256){
        int m = idx>>7, o = idx&127;
        float h0=0.f, c0=0.f;
        #pragma unroll 4
        for (int n=0;n<NN;n++){
            float gm = sG[m*NN+n];
            h0 = fmaf(gm, sY1[n*128+o], h0);
            c0 = fmaf(gm, sY2[n*128+o], c0);
        }
        long off = ((long)m*Bb + b)*128 + o;
        g_c1[off]=c0; g_c2[off]=c0;
        half h,l; splitH(h0, h, l);
        g_h1H[off]=h; g_h1L[off]=l;
        g_h2H[off]=h; g_h2L[off]=l;
    }
}

__global__ void init_xi(const float* __restrict__ x, const float* __restrict__ z)
{
    int i = blockIdx.x*blockDim.x + threadIdx.x;
    if (i < NN*Bb*80){
        int f = i % 80, nb = i / 80;
        int b = nb % Bb, n = nb / Bb;
        float v = 0.f;
        if (f < 64)      v = z[(b*NN + n)*64 + f];
        else if (f < 72) v = x[(b*NN + n)*8 + (f-64)];
        half h,l; splitH(v, h, l);
        g_xiH[i]=h; g_xiL[i]=l;
    }
    if (i < Bb*NN*4){
        int j = i % 4, bn = i / 4;
        g_locstart[i] = x[bn*8 + j];
    }
}

// ---------------------------------------------------------------------------
// weight prepack: fp32 -> hi/lo fp16 with K padding + concat placement
// ---------------------------------------------------------------------------
__global__ void prep_w(const float* __restrict__ src, half* __restrict__ dH,
                       half* __restrict__ dL, int Ksrc, int Osrc,
                       int Kdst, int Odst, int rowOff, int colOff, int rows)
{
    long total = (long)NN*rows*Osrc;
    for (long idx = blockIdx.x*blockDim.x + threadIdx.x; idx < total;
         idx += (long)gridDim.x*blockDim.x){
        int o = idx % Osrc;
        int r = (idx / Osrc) % rows;
        int n = idx / ((long)Osrc*rows);
        float v = (r < Ksrc) ? src[((long)n*Ksrc + r)*Osrc + o] : 0.f;
        half h,l; splitH(v, h, l);
        long di = ((long)n*Kdst + rowOff + r)*Odst + colOff + o;
        dH[di]=h; dL[di]=l;
    }
}

__global__ void prep_bias(const float* __restrict__ b1, const float* __restrict__ b2)
{
    int i = blockIdx.x*blockDim.x + threadIdx.x;
    if (i < NN*256){
        int n = i >> 8, j = i & 255;
        g_fcBc[i] = (j < 128) ? b1[n*128 + j] : b2[n*128 + (j-128)];
    }
}

// ---------------------------------------------------------------------------
extern "C" void kernel_launch(void* const* d_in, const int* in_sizes, int n_in,
                              void* d_out, int out_size)
{
    const float* x    = (const float*)d_in[0];
    const float* enc  = (const float*)d_in[1];
    const float* z    = (const float*)d_in[2];
    const float* G    = (const float*)d_in[4];
    const float* Wx0  = (const float*)d_in[5];
    const float* Wh0  = (const float*)d_in[6];
    const float* b0_  = (const float*)d_in[7];
    const float* Wx1  = (const float*)d_in[8];
    const float* Wh1  = (const float*)d_in[9];
    const float* b1_  = (const float*)d_in[10];
    const float* fcW  = (const float*)d_in[11];
    const float* fcB  = (const float*)d_in[12];
    const float* fc2W = (const float*)d_in[13];
    const float* fc2B = (const float*)d_in[14];
    const float* ih1W = (const float*)d_in[15];
    const float* ih1B = (const float*)d_in[16];
    const float* ih2W = (const float*)d_in[17];
    const float* ih2B = (const float*)d_in[18];
    const float* locW = (const float*)d_in[19];
    const float* locB = (const float*)d_in[20];
    const float* lzW  = (const float*)d_in[21];
    const float* lzB  = (const float*)d_in[22];
    float* out = (float*)d_out;

    half *xiH,*xiL,*h1H,*h1L,*h2H,*h2L,*yiH,*yiL;
    half *w0H,*w0L,*w1H,*w1L,*wfH,*wfL;
    float *c1,*c2,*gates,*fcpre,*fcBc;
    cudaGetSymbolAddress((void**)&xiH, g_xiH); cudaGetSymbolAddress((void**)&xiL, g_xiL);
    cudaGetSymbolAddress((void**)&h1H, g_h1H); cudaGetSymbolAddress((void**)&h1L, g_h1L);
    cudaGetSymbolAddress((void**)&h2H, g_h2H); cudaGetSymbolAddress((void**)&h2L, g_h2L);
    cudaGetSymbolAddress((void**)&yiH, g_yiH); cudaGetSymbolAddress((void**)&yiL, g_yiL);
    cudaGetSymbolAddress((void**)&w0H, g_w0H); cudaGetSymbolAddress((void**)&w0L, g_w0L);
    cudaGetSymbolAddress((void**)&w1H, g_w1H); cudaGetSymbolAddress((void**)&w1L, g_w1L);
    cudaGetSymbolAddress((void**)&wfH, g_wfH); cudaGetSymbolAddress((void**)&wfL, g_wfL);
    cudaGetSymbolAddress((void**)&c1, g_c1);   cudaGetSymbolAddress((void**)&c2, g_c2);
    cudaGetSymbolAddress((void**)&gates, g_gates);
    cudaGetSymbolAddress((void**)&fcpre, g_fcpre);
    cudaGetSymbolAddress((void**)&fcBc, g_fcBc);

    const int smem_head = (NN*256 + NN*256 + NN*NN + NN*8 + 128*3 + 128*4)*4;
    const int smem_init = (NN*256 + NN*128 + NN*128 + NN*NN)*4;
    cudaFuncSetAttribute(head_kernel,cudaFuncAttributeMaxDynamicSharedMemorySize, smem_head);
    cudaFuncSetAttribute(init_state, cudaFuncAttributeMaxDynamicSharedMemorySize, smem_init);

    // ---- prepack weights (once per launch) ----
    prep_w<<<2048,256>>>(Wx0, w0H, w0L,  72, 512, 208, 512,   0, 0,  80);
    prep_w<<<2048,256>>>(Wh0, w0H, w0L, 128, 512, 208, 512,  80, 0, 128);
    prep_w<<<2048,256>>>(Wx1, w1H, w1L, 128, 512, 256, 512,   0, 0, 128);
    prep_w<<<2048,256>>>(Wh1, w1H, w1L, 128, 512, 256, 512, 128, 0, 128);
    prep_w<<<1024,256>>>(fcW,  wfH, wfL, 128, 128, 128, 256,   0, 0,   128);
    prep_w<<<1024,256>>>(fc2W, wfH, wfL, 128, 128, 128, 256,   0, 128, 128);
    prep_bias<<<(NN*256+255)/256,256>>>(fcB, fc2B);

    init_state<<<Bb, 256, smem_init>>>(enc, G, ih1W, ih1B, ih2W, ih2B);
    init_xi<<<(NN*Bb*80 + 255)/256, 256>>>(x, z);

    dim3 gl(NN, 4, Bb/64);   // lstm gemms: O=512
    dim3 gf(NN, 2, Bb/64);   // fc gemm:   O=256
    dim3 gm(Bb, 4);

    for (int t = 0; t < TT; t++){
        gemm_fp16<<<gl, 256>>>(xiH, xiL, 5, 80,  h1H, h1L, 8, 128,
                               w0H, w0L, 208, b0_, 512, gates);
        lstm_mix <<<gm, 128>>>(gates, G, c1, c1, h1H, h1L, nullptr, nullptr);
        gemm_fp16<<<gl, 256>>>(h1H, h1L, 8, 128, h2H, h2L, 8, 128,
                               w1H, w1L, 256, b1_, 512, gates);
        lstm_mix <<<gm, 128>>>(gates, G, c2, c2, h2H, h2L, yiH, yiL);
        gemm_fp16<<<gf, 256>>>(yiH, yiL, 8, 128, (half*)nullptr, (half*)nullptr, 0, 0,
                               wfH, wfL, 128, fcBc, 256, fcpre);
        head_kernel<<<Bb, 256, smem_head>>>(G, locW, locB, lzW, lzB, out, t);
    }
}